// round 1
// baseline (speedup 1.0000x reference)
#include <cuda_runtime.h>
#include <cstdint>

#define N_EMBED   1024
#define EMBED_DIM 256
#define N_ROWS    65536
#define MTILE     128
#define NTILE     128
#define ZQ_ELEMS  (N_ROWS * EMBED_DIM)

#define ZS_STRIDE 132
#define ES_STRIDE 132
// smem layout (floats): z_s [256][132], e_s [128][132], e2_s [1024], then keys (128 x u64)
#define ZS_FLOATS (256 * ZS_STRIDE)
#define ES_FLOATS (128 * ES_STRIDE)
#define SMEM_BYTES ((ZS_FLOATS + ES_FLOATS + 1024) * 4 + 128 * 8)

__device__ float g_e2[N_EMBED];

// ||e_n||^2, one warp per code row
__global__ void e2_kernel(const float* __restrict__ emb) {
    int w = (blockIdx.x * blockDim.x + threadIdx.x) >> 5;
    int lane = threadIdx.x & 31;
    if (w >= N_EMBED) return;
    const float* row = emb + (size_t)w * EMBED_DIM;
    float s = 0.f;
    #pragma unroll
    for (int k = 0; k < EMBED_DIM / 32; k++) {
        float v = row[lane + k * 32];
        s = fmaf(v, v, s);
    }
    #pragma unroll
    for (int off = 16; off; off >>= 1) s += __shfl_xor_sync(0xffffffffu, s, off);
    if (lane == 0) g_e2[w] = s;
}

__device__ __forceinline__ unsigned long long pack_dup(float a) {
    unsigned long long r;
    asm("mov.b64 %0, {%1, %1};" : "=l"(r) : "f"(a));
    return r;
}
__device__ __forceinline__ void fma2(unsigned long long& d, unsigned long long a, unsigned long long b) {
    asm("fma.rn.f32x2 %0, %1, %2, %0;" : "+l"(d) : "l"(a), "l"(b));
}
__device__ __forceinline__ void unpack2(unsigned long long v, float& lo, float& hi) {
    asm("mov.b64 {%0, %1}, %2;" : "=f"(lo), "=f"(hi) : "l"(v));
}
__device__ __forceinline__ unsigned ordf(float f) {
    unsigned u = __float_as_uint(f);
    return (u & 0x80000000u) ? ~u : (u | 0x80000000u);
}

__global__ void __launch_bounds__(256)
vq_kernel(const float* __restrict__ z, const float* __restrict__ emb, float* __restrict__ out) {
    extern __shared__ float sm[];
    float* z_s  = sm;                      // [256][132] k-major
    float* e_s  = sm + ZS_FLOATS;          // [128][132] k-major (one K-half of an N-chunk)
    float* e2_s = sm + ZS_FLOATS + ES_FLOATS;
    unsigned long long* key_s = (unsigned long long*)(e2_s + 1024);

    const int tid = threadIdx.x;
    const int tx = tid & 15;   // n direction (8 codes each)
    const int ty = tid >> 4;   // m direction (8 rows each)
    const int row_base = blockIdx.x * MTILE;

    // e2 into smem
    for (int i = tid; i < N_EMBED; i += 256) e2_s[i] = g_e2[i];

    // load + transpose z tile: z_s[k][r]
    {
        const float4* zg = (const float4*)(z + (size_t)row_base * EMBED_DIM);
        for (int it = tid; it < 128 * 64; it += 256) {
            int r  = it & 127;
            int k4 = it >> 7;
            float4 v = zg[r * 64 + k4];
            int k = k4 * 4;
            z_s[(k + 0) * ZS_STRIDE + r] = v.x;
            z_s[(k + 1) * ZS_STRIDE + r] = v.y;
            z_s[(k + 2) * ZS_STRIDE + r] = v.z;
            z_s[(k + 3) * ZS_STRIDE + r] = v.w;
        }
    }

    unsigned long long keys[8];
    #pragma unroll
    for (int i = 0; i < 8; i++) keys[i] = 0xFFFFFFFFFFFFFFFFull;

    for (int nc = 0; nc < N_EMBED / NTILE; nc++) {
        unsigned long long acc[8][4];
        #pragma unroll
        for (int i = 0; i < 8; i++)
            #pragma unroll
            for (int j = 0; j < 4; j++) acc[i][j] = 0ull;

        for (int kh = 0; kh < 2; kh++) {
            __syncthreads();  // protect e_s (and first time, z_s ordering)
            const float* eg = emb + (size_t)(nc * NTILE) * EMBED_DIM + kh * 128;
            for (int it = tid; it < 128 * 32; it += 256) {
                int n  = it & 127;
                int k4 = it >> 7;
                float4 v = *(const float4*)(eg + n * EMBED_DIM + k4 * 4);
                int k = k4 * 4;
                e_s[(k + 0) * ES_STRIDE + n] = v.x;
                e_s[(k + 1) * ES_STRIDE + n] = v.y;
                e_s[(k + 2) * ES_STRIDE + n] = v.z;
                e_s[(k + 3) * ES_STRIDE + n] = v.w;
            }
            __syncthreads();

            const float* zh = z_s + kh * 128 * ZS_STRIDE + ty * 8;
            const float* eh = e_s + tx * 8;
            #pragma unroll 2
            for (int k = 0; k < 128; k++) {
                float4 a0 = *(const float4*)(zh + k * ZS_STRIDE);
                float4 a1 = *(const float4*)(zh + k * ZS_STRIDE + 4);
                const unsigned long long* bb = (const unsigned long long*)(eh + k * ES_STRIDE);
                unsigned long long b0 = bb[0], b1 = bb[1], b2 = bb[2], b3 = bb[3];
                float av[8] = {a0.x, a0.y, a0.z, a0.w, a1.x, a1.y, a1.z, a1.w};
                #pragma unroll
                for (int i = 0; i < 8; i++) {
                    unsigned long long a2 = pack_dup(av[i]);
                    fma2(acc[i][0], a2, b0);
                    fma2(acc[i][1], a2, b1);
                    fma2(acc[i][2], a2, b2);
                    fma2(acc[i][3], a2, b3);
                }
            }
        }

        // fold this n-chunk into running argmin keys
        #pragma unroll
        for (int i = 0; i < 8; i++) {
            #pragma unroll
            for (int j = 0; j < 4; j++) {
                float dlo, dhi;
                unpack2(acc[i][j], dlo, dhi);
                int n0 = nc * NTILE + tx * 8 + j * 2;
                float dist0 = fmaf(-2.f, dlo, e2_s[n0]);
                float dist1 = fmaf(-2.f, dhi, e2_s[n0 + 1]);
                unsigned long long k0 = ((unsigned long long)ordf(dist0) << 32) | (unsigned)n0;
                unsigned long long k1 = ((unsigned long long)ordf(dist1) << 32) | (unsigned)(n0 + 1);
                if (k0 < keys[i]) keys[i] = k0;
                if (k1 < keys[i]) keys[i] = k1;
            }
        }
    }

    // reduce over the 16 n-threads (tx) within each half-warp
    #pragma unroll
    for (int off = 1; off < 16; off <<= 1) {
        #pragma unroll
        for (int i = 0; i < 8; i++) {
            unsigned long long o = __shfl_xor_sync(0xffffffffu, keys[i], off);
            if (o < keys[i]) keys[i] = o;
        }
    }
    if (tx == 0) {
        #pragma unroll
        for (int i = 0; i < 8; i++) key_s[ty * 8 + i] = keys[i];
    }
    __syncthreads();

    // indices (as float) into the tail of d_out
    if (tid < 128) {
        unsigned idx = (unsigned)(key_s[tid] & 0xffffffffull);
        out[(size_t)ZQ_ELEMS + row_base + tid] = (float)idx;
    }

    // z_q gather: copy chosen emb rows
    float4* outq = (float4*)out;
    for (int it = tid; it < 128 * 64; it += 256) {
        int r  = it >> 6;
        int c4 = it & 63;
        unsigned idx = (unsigned)(key_s[r] & 0xffffffffull);
        float4 v = *(const float4*)(emb + (size_t)idx * EMBED_DIM + c4 * 4);
        outq[(size_t)(row_base + r) * 64 + c4] = v;
    }
}

extern "C" void kernel_launch(void* const* d_in, const int* in_sizes, int n_in,
                              void* d_out, int out_size) {
    const float* z   = (const float*)d_in[0];
    const float* emb = (const float*)d_in[1];
    float* out = (float*)d_out;

    e2_kernel<<<N_EMBED / 8, 256>>>(emb);

    cudaFuncSetAttribute(vq_kernel, cudaFuncAttributeMaxDynamicSharedMemorySize, SMEM_BYTES);
    vq_kernel<<<N_ROWS / MTILE, 256, SMEM_BYTES>>>(z, emb, out);
}

// round 2
// speedup vs baseline: 1.1961x; 1.1961x over previous
#include <cuda_runtime.h>
#include <cstdint>

#define N_EMBED   1024
#define EMBED_DIM 256
#define N_ROWS    65536
#define MTILE     128
#define NTILE     128
#define KC        64
#define ZQ_ELEMS  (N_ROWS * EMBED_DIM)

typedef unsigned long long u64;

// smem floats: z_s [64][128], e_s [64][128], e2_s [1024], keys 128*u64 (=256 floats)
#define ZS_FLOATS (KC * 128)
#define ES_FLOATS (KC * 128)
#define SMEM_FLOATS (ZS_FLOATS + ES_FLOATS + 1024 + 256)
#define SMEM_BYTES (SMEM_FLOATS * 4)

__device__ float g_e2[N_EMBED];

__global__ void e2_kernel(const float* __restrict__ emb) {
    int w = (blockIdx.x * blockDim.x + threadIdx.x) >> 5;
    int lane = threadIdx.x & 31;
    if (w >= N_EMBED) return;
    const float* row = emb + (size_t)w * EMBED_DIM;
    float s = 0.f;
    #pragma unroll
    for (int k = 0; k < EMBED_DIM / 32; k++) {
        float v = row[lane + k * 32];
        s = fmaf(v, v, s);
    }
    #pragma unroll
    for (int off = 16; off; off >>= 1) s += __shfl_xor_sync(0xffffffffu, s, off);
    if (lane == 0) g_e2[w] = s;
}

__device__ __forceinline__ u64 pack_dup(float a) {
    u64 r;
    asm("mov.b64 %0, {%1, %1};" : "=l"(r) : "f"(a));
    return r;
}
__device__ __forceinline__ void fma2(u64& d, u64 a, u64 b) {
    asm("fma.rn.f32x2 %0, %1, %2, %0;" : "+l"(d) : "l"(a), "l"(b));
}
__device__ __forceinline__ void unpack2(u64 v, float& lo, float& hi) {
    asm("mov.b64 {%0, %1}, %2;" : "=f"(lo), "=f"(hi) : "l"(v));
}
__device__ __forceinline__ unsigned ordf(float f) {
    unsigned u = __float_as_uint(f);
    return (u & 0x80000000u) ? ~u : (u | 0x80000000u);
}

__global__ void __launch_bounds__(256, 2)
vq_kernel(const float* __restrict__ z, const float* __restrict__ emb, float* __restrict__ out) {
    extern __shared__ float sm[];
    float* z_s  = sm;                       // [KC][128], col swizzled by (k&28)
    float* e_s  = sm + ZS_FLOATS;           // [KC][128], col swizzled by (k&28)
    float* e2_s = sm + ZS_FLOATS + ES_FLOATS;
    u64*   key_s = (u64*)(e2_s + 1024);

    const int tid = threadIdx.x;
    const int tx = tid & 15;    // n direction: pairs n = 32*j + 2*tx
    const int ty = tid >> 4;    // m direction: rows ty*8 .. ty*8+7
    const int row_base = blockIdx.x * MTILE;

    for (int i = tid; i < N_EMBED; i += 256) e2_s[i] = g_e2[i];

    u64 keys[8];
    #pragma unroll
    for (int i = 0; i < 8; i++) keys[i] = 0xFFFFFFFFFFFFFFFFull;

    const int zcol0 = (ty * 8);
    const int zcol1 = (ty * 8 + 4);

    for (int nc = 0; nc < N_EMBED / NTILE; nc++) {
        u64 acc[8][4];
        #pragma unroll
        for (int i = 0; i < 8; i++)
            #pragma unroll
            for (int j = 0; j < 4; j++) acc[i][j] = 0ull;

        for (int kc = 0; kc < EMBED_DIM / KC; kc++) {
            __syncthreads();
            // ---- stage z chunk [128 rows][KC k] transposed+swizzled ----
            {
                const float* zg = z + (size_t)row_base * EMBED_DIM + kc * KC;
                #pragma unroll
                for (int t = 0; t < 8; t++) {
                    int idx = tid + t * 256;     // 0..2047
                    int r  = idx >> 4;           // 0..127
                    int k4 = idx & 15;           // float4 index in k
                    float4 v = *(const float4*)(zg + (size_t)r * EMBED_DIM + k4 * 4);
                    int k = k4 * 4;
                    int kx = k & 28;             // same for k..k+3
                    int col = r ^ kx;
                    z_s[(k + 0) * 128 + col] = v.x;
                    z_s[(k + 1) * 128 + col] = v.y;
                    z_s[(k + 2) * 128 + col] = v.z;
                    z_s[(k + 3) * 128 + col] = v.w;
                }
            }
            // ---- stage e chunk [128 codes][KC k] transposed+swizzled ----
            {
                const float* eg = emb + (size_t)(nc * NTILE) * EMBED_DIM + kc * KC;
                #pragma unroll
                for (int t = 0; t < 8; t++) {
                    int idx = tid + t * 256;
                    int n  = idx >> 4;
                    int k4 = idx & 15;
                    float4 v = *(const float4*)(eg + (size_t)n * EMBED_DIM + k4 * 4);
                    int k = k4 * 4;
                    int kx = k & 28;
                    int col = n ^ kx;
                    e_s[(k + 0) * 128 + col] = v.x;
                    e_s[(k + 1) * 128 + col] = v.y;
                    e_s[(k + 2) * 128 + col] = v.z;
                    e_s[(k + 3) * 128 + col] = v.w;
                }
            }
            __syncthreads();

            // ---- accumulate 2*z.e over this k chunk ----
            #pragma unroll 4
            for (int k = 0; k < KC; k++) {
                const int kx = k & 28;
                const float* zk = z_s + k * 128;
                const float* ek = e_s + k * 128;
                float4 a0 = *(const float4*)(zk + (zcol0 ^ kx));
                float4 a1 = *(const float4*)(zk + (zcol1 ^ kx));
                u64 b0 = *(const u64*)(ek + ((2 * tx +  0) ^ kx));
                u64 b1 = *(const u64*)(ek + ((2 * tx + 32) ^ kx));
                u64 b2 = *(const u64*)(ek + ((2 * tx + 64) ^ kx));
                u64 b3 = *(const u64*)(ek + ((2 * tx + 96) ^ kx));
                float av[8] = {a0.x, a0.y, a0.z, a0.w, a1.x, a1.y, a1.z, a1.w};
                #pragma unroll
                for (int i = 0; i < 8; i++) {
                    u64 a2 = pack_dup(av[i]);
                    fma2(acc[i][0], a2, b0);
                    fma2(acc[i][1], a2, b1);
                    fma2(acc[i][2], a2, b2);
                    fma2(acc[i][3], a2, b3);
                }
            }
        }

        // ---- fold n-chunk into running argmin keys ----
        #pragma unroll
        for (int i = 0; i < 8; i++) {
            #pragma unroll
            for (int j = 0; j < 4; j++) {
                float dlo, dhi;
                unpack2(acc[i][j], dlo, dhi);
                int n0 = nc * NTILE + 32 * j + 2 * tx;
                float dist0 = fmaf(-2.f, dlo, e2_s[n0]);
                float dist1 = fmaf(-2.f, dhi, e2_s[n0 + 1]);
                u64 k0 = ((u64)ordf(dist0) << 32) | (unsigned)n0;
                u64 k1 = ((u64)ordf(dist1) << 32) | (unsigned)(n0 + 1);
                if (k0 < keys[i]) keys[i] = k0;
                if (k1 < keys[i]) keys[i] = k1;
            }
        }
    }

    // reduce across the 16 n-threads sharing each row group
    #pragma unroll
    for (int off = 1; off < 16; off <<= 1) {
        #pragma unroll
        for (int i = 0; i < 8; i++) {
            u64 o = __shfl_xor_sync(0xffffffffu, keys[i], off);
            if (o < keys[i]) keys[i] = o;
        }
    }
    if (tx == 0) {
        #pragma unroll
        for (int i = 0; i < 8; i++) key_s[ty * 8 + i] = keys[i];
    }
    __syncthreads();

    // indices (as float) into tail of d_out
    if (tid < 128) {
        unsigned idx = (unsigned)(key_s[tid] & 0xffffffffull);
        out[(size_t)ZQ_ELEMS + row_base + tid] = (float)idx;
    }

    // z_q gather
    float4* outq = (float4*)out;
    for (int it = tid; it < 128 * 64; it += 256) {
        int r  = it >> 6;
        int c4 = it & 63;
        unsigned idx = (unsigned)(key_s[r] & 0xffffffffull);
        float4 v = *(const float4*)(emb + (size_t)idx * EMBED_DIM + c4 * 4);
        outq[(size_t)(row_base + r) * 64 + c4] = v;
    }
}

extern "C" void kernel_launch(void* const* d_in, const int* in_sizes, int n_in,
                              void* d_out, int out_size) {
    const float* z   = (const float*)d_in[0];
    const float* emb = (const float*)d_in[1];
    float* out = (float*)d_out;

    e2_kernel<<<N_EMBED / 8, 256>>>(emb);

    cudaFuncSetAttribute(vq_kernel, cudaFuncAttributeMaxDynamicSharedMemorySize, SMEM_BYTES);
    vq_kernel<<<N_ROWS / MTILE, 256, SMEM_BYTES>>>(z, emb, out);
}